// round 16
// baseline (speedup 1.0000x reference)
#include <cuda_runtime.h>
#include <cuda_bf16.h>
#include <cstdint>

// Problem constants
constexpr int B_ = 256;   // batch
constexpr int T_ = 128;   // trees
constexpr int N_ = 256;   // nodes (= classes)
constexpr int E_ = 64;    // embedding
constexpr int H_ = 16;    // hidden
constexpr int K2_ = (T_ - 1) * H_;  // 2032

// Fragment-ordered gathered embeddings:
// g_bef[ ((j*16 + strip)*4 + kt)*32 + lane ] = uint4 A-frag regs {a0,a1,a2,a3}
__device__ uint4 g_bef[T_ * 16 * 4 * 32];   // 4 MB

// ---------------------------------------------------------------------------
// mma.sync m16n8k16 bf16 (fp32 accum) + ldmatrix + mbarrier helpers
// ---------------------------------------------------------------------------
__device__ __forceinline__ void mma_bf16(float* c, const uint32_t* a,
                                         uint32_t b0, uint32_t b1) {
    asm volatile(
        "mma.sync.aligned.m16n8k16.row.col.f32.bf16.bf16.f32 "
        "{%0,%1,%2,%3}, {%4,%5,%6,%7}, {%8,%9}, {%0,%1,%2,%3};"
        : "+f"(c[0]), "+f"(c[1]), "+f"(c[2]), "+f"(c[3])
        : "r"(a[0]), "r"(a[1]), "r"(a[2]), "r"(a[3]), "r"(b0), "r"(b1));
}

#define LDSM_X4(r0, r1, r2, r3, addr)                                     \
    asm volatile("ldmatrix.sync.aligned.m8n8.x4.shared.b16 "              \
                 "{%0,%1,%2,%3}, [%4];"                                   \
                 : "=r"(r0), "=r"(r1), "=r"(r2), "=r"(r3) : "r"(addr))

#define MBAR_INIT(a, c) \
    asm volatile("mbarrier.init.shared.b64 [%0], %1;" :: "r"(a), "r"(c) : "memory")
#define MBAR_ARRIVE(a) \
    asm volatile("mbarrier.arrive.shared.b64 _, [%0];" :: "r"(a) : "memory")
#define MBAR_WAIT(a, par) do {                                              \
    uint32_t _m = (a), _p = (par), _d;                                      \
    asm volatile("{\n\t.reg .pred p;\n\t"                                   \
        "mbarrier.try_wait.parity.acquire.cta.shared::cta.b64 p, [%1], %2;\n\t" \
        "selp.b32 %0, 1, 0, p;\n\t}" : "=r"(_d) : "r"(_m), "r"(_p) : "memory"); \
    if (!_d) {                                                              \
        asm volatile("{\n\t.reg .pred P1;\n\tWL_%=:\n\t"                    \
            "mbarrier.try_wait.parity.acquire.cta.shared::cta.b64 P1, [%0], %1, 0x989680;\n\t" \
            "@P1 bra.uni WD_%=;\n\tbra.uni WL_%=;\n\tWD_%=:\n\t}"           \
            :: "r"(_m), "r"(_p) : "memory");                                \
    }                                                                       \
} while (0)

// ---------------------------------------------------------------------------
// Kernel 1: gather embeddings (shifted index) AND emit A-fragments.
// ---------------------------------------------------------------------------
__global__ void __launch_bounds__(256)
gather_frag_kernel(const int* __restrict__ x,
                   const float* __restrict__ emb) {
    __shared__ __align__(16) char sm[256 * 144];
    const int j    = blockIdx.x;
    const int tid  = threadIdx.x;
    const int w    = tid >> 5;
    const int lane = tid & 31;
    const uint32_t smem_u32 = (uint32_t)__cvta_generic_to_shared(sm);

    {
        const int row = x[tid * T_ + j] + j * N_;
        const float4* src =
            reinterpret_cast<const float4*>(emb + (size_t)row * E_);
        char* dst = sm + tid * 144;
#pragma unroll
        for (int k = 0; k < 8; ++k) {
            float4 f0 = src[2 * k], f1 = src[2 * k + 1];
            __nv_bfloat162 p0 = __floats2bfloat162_rn(f0.x, f0.y);
            __nv_bfloat162 p1 = __floats2bfloat162_rn(f0.z, f0.w);
            __nv_bfloat162 p2 = __floats2bfloat162_rn(f1.x, f1.y);
            __nv_bfloat162 p3 = __floats2bfloat162_rn(f1.z, f1.w);
            uint4 v;
            v.x = *reinterpret_cast<uint32_t*>(&p0);
            v.y = *reinterpret_cast<uint32_t*>(&p1);
            v.z = *reinterpret_cast<uint32_t*>(&p2);
            v.w = *reinterpret_cast<uint32_t*>(&p3);
            *reinterpret_cast<uint4*>(dst + k * 16) = v;
        }
    }
    __syncthreads();

#pragma unroll
    for (int sg = 0; sg < 2; ++sg) {
        const int s = w + 8 * sg;
        const uint32_t a_off = smem_u32 +
            (s * 16 + (lane & 15)) * 144 + (lane >> 4) * 16;
#pragma unroll
        for (int kt = 0; kt < 4; ++kt) {
            uint32_t r0, r1, r2, r3;
            LDSM_X4(r0, r1, r2, r3, a_off + kt * 32);
            uint4 v; v.x = r0; v.y = r1; v.z = r2; v.w = r3;
            g_bef[((size_t)(j * 16 + s) * 4 + kt) * 32 + lane] = v;
        }
    }
}

// ---------------------------------------------------------------------------
// Fused-kernel SMEM layout (bytes)
// ---------------------------------------------------------------------------
constexpr int W1_STRIDE = 144;              // [h][e] bf16
constexpr int W1_BUF    = 16 * W1_STRIDE;   // 2304
constexpr int W2_STRIDE = 48;               // [e][h] bf16
constexpr int W2_BUF    = 64 * W2_STRIDE;   // 3072
constexpr int NSTAGE    = 4;
constexpr int OFF_MBAR  = 0;                          // 8 mbarriers (64B)
constexpr int OFF_W1    = 64;                         // 4 bufs
constexpr int OFF_W2    = OFF_W1 + NSTAGE * W1_BUF;   // 9280
constexpr int OFF_B1    = OFF_W2 + NSTAGE * W2_BUF;   // 21568
constexpr int OFF_B2    = OFF_B1 + T_ * H_ * 4;       // 29760
constexpr int OFF_W3S   = 30016;                      // 256 rows x 144B
constexpr int SMEM_TOTAL = OFF_W3S + 256 * 144;       // 66880

constexpr int NTHREADS  = 288;   // 8 consumer warps (m32) + 1 producer warp

// ---------------------------------------------------------------------------
// Kernel 2: warp-specialized fused stages 2..7. CTA = tree i.
// Consumers (warps 0-7): m32 strip each (2 m-tiles share one W-frag load),
//   A via direct LDG of g_bef (prefetch 1), W via 4-deep mbarrier ring.
// Producer (warp 8): LDG fp32 weights -> cvt bf16 -> STS ring.
// NO __syncthreads in the mainloop.
// ---------------------------------------------------------------------------
__global__ void __launch_bounds__(NTHREADS, 1)
fused_all_kernel(const float* __restrict__ lin1,   // [T,T,E,H]
                 const float* __restrict__ b1,     // [T,T,H]
                 const float* __restrict__ lin2,   // [T,(T-1)*H,E]
                 const float* __restrict__ b2,     // [T,E]
                 const float* __restrict__ w3g,    // [T,E,N]
                 const int*   __restrict__ x,      // [B,T]
                 float* __restrict__ out) {        // [B,T]
    extern __shared__ char smem[];
    const int i    = blockIdx.x;
    const int tid  = threadIdx.x;
    const int w    = tid >> 5;
    const int lane = tid & 31;
    const int q    = lane & 3;
    const int r4   = lane >> 2;

    float* sb1 = reinterpret_cast<float*>(smem + OFF_B1);
    float* sb2 = reinterpret_cast<float*>(smem + OFF_B2);
    const uint32_t smem_u32 = (uint32_t)__cvta_generic_to_shared(smem);
    const uint32_t mb_full  = smem_u32 + OFF_MBAR;        // full[s]  = +8s
    const uint32_t mb_empty = smem_u32 + OFF_MBAR + 32;   // empty[s] = +8s

    auto jof = [&](int jj) { return jj + (jj >= i); };

    // ---- init: mbarriers + biases, one barrier before pipeline start -------
    if (tid == 0) {
#pragma unroll
        for (int s = 0; s < NSTAGE; ++s) {
            MBAR_INIT(mb_full + 8 * s, 32);    // 32 producer threads arrive
            MBAR_INIT(mb_empty + 8 * s, 256);  // 256 consumer threads arrive
        }
    }
    if (tid < 256) {
#pragma unroll
        for (int u = 0; u < 8; ++u)
            sb1[tid + 256 * u] = b1[(size_t)i * T_ * H_ + tid + 256 * u];
        if (tid < E_) sb2[tid] = b2[(size_t)i * E_ + tid];
    }
    __syncthreads();

    if (w == 8) {
        // =================== PRODUCER (warp 8) ==============================
        const int ptid = lane;                 // 0..31
        for (int jj = 0; jj < T_ - 1; ++jj) {
            const int s = jj & 3;
            const int j = jof(jj);
            MBAR_WAIT(mb_empty + 8 * s, ((jj >> 2) & 1) ^ 1);

            // W1[i,j]: thread owns e = 2*ptid + {0,1} (16 floats each)
            {
                const float4* p = reinterpret_cast<const float4*>(
                    lin1 + (size_t)(i * T_ + j) * (E_ * H_) + ptid * 32);
                __nv_bfloat16* w1 = reinterpret_cast<__nv_bfloat16*>(
                    smem + OFF_W1 + s * W1_BUF);
#pragma unroll
                for (int v4 = 0; v4 < 8; ++v4) {
                    float4 f = p[v4];
                    const float* fv = reinterpret_cast<const float*>(&f);
                    int e = ptid * 2 + (v4 >> 2);
#pragma unroll
                    for (int u = 0; u < 4; ++u) {
                        int h = (v4 & 3) * 4 + u;
                        w1[h * (W1_STRIDE / 2) + e] = __float2bfloat16(fv[u]);
                    }
                }
            }
            // W2 rows: thread owns idx = ptid*32 + 0..31
            {
                const int kk = (j < i) ? j : j - 1;
                const float4* p = reinterpret_cast<const float4*>(
                    lin2 + ((size_t)i * K2_ + (size_t)kk * H_) * E_ + ptid * 32);
                __nv_bfloat16* w2 = reinterpret_cast<__nv_bfloat16*>(
                    smem + OFF_W2 + s * W2_BUF);
#pragma unroll
                for (int v4 = 0; v4 < 8; ++v4) {
                    float4 f = p[v4];
                    const float* fv = reinterpret_cast<const float*>(&f);
#pragma unroll
                    for (int u = 0; u < 4; ++u) {
                        int idx = ptid * 32 + v4 * 4 + u;
                        int k = idx >> 6, e = idx & 63;
                        w2[e * (W2_STRIDE / 2) + k] = __float2bfloat16(fv[u]);
                    }
                }
            }
            MBAR_ARRIVE(mb_full + 8 * s);      // release: STS visible
        }
        // join the two consumer barriers, then exit
        __syncthreads();
        __syncthreads();
        return;
    }

    // =================== CONSUMER (warps 0-7, m32) ==========================
    const int brow = (lane & 7) + ((lane >> 1) & 8);
    const int bcol = ((lane >> 3) & 1) * 16;
    const uint32_t w1_off = smem_u32 + OFF_W1 + brow * W1_STRIDE + bcol;
    const uint32_t w2_off = smem_u32 + OFF_W2 + brow * W2_STRIDE + bcol;

    // A-fragments: strips 2w (mt=0) and 2w+1 (mt=1)
    auto ldg_a = [&](int j, uint4 (*a)[4]) {
#pragma unroll
        for (int mt = 0; mt < 2; ++mt) {
            const uint4* p =
                g_bef + (size_t)(j * 16 + 2 * w + mt) * 4 * 32 + lane;
#pragma unroll
            for (int kt = 0; kt < 4; ++kt) a[mt][kt] = p[kt * 32];
        }
    };

    uint4 a_cur[2][4], a_nxt[2][4];
    ldg_a(jof(0), a_cur);

    float zacc[2][8][4];
#pragma unroll
    for (int mt = 0; mt < 2; ++mt)
#pragma unroll
        for (int nt = 0; nt < 8; ++nt)
#pragma unroll
            for (int s = 0; s < 4; ++s) zacc[mt][nt][s] = 0.f;

    for (int jj = 0; jj < T_ - 1; ++jj) {
        const int s = jj & 3;
        const int j = jof(jj);

        if (jj + 1 < T_ - 1) ldg_a(jof(jj + 1), a_nxt);

        MBAR_WAIT(mb_full + 8 * s, (jj >> 2) & 1);   // acquire

        const uint32_t w1b = w1_off + s * W1_BUF;
        const uint32_t w2b = w2_off + s * W2_BUF;

        // GEMM1: tmp[32,16] = BE[32,64] @ W1[64,16] (+bias1)
        float c1[2][2][4];
#pragma unroll
        for (int mt = 0; mt < 2; ++mt)
#pragma unroll
            for (int nt = 0; nt < 2; ++nt) {
                float bv0 = sb1[j * H_ + nt * 8 + 2 * q];
                float bv1 = sb1[j * H_ + nt * 8 + 2 * q + 1];
                c1[mt][nt][0] = bv0; c1[mt][nt][1] = bv1;
                c1[mt][nt][2] = bv0; c1[mt][nt][3] = bv1;
            }
#pragma unroll
        for (int kt = 0; kt < 4; ++kt) {
            uint32_t b0, b1r, b2r, b3;
            LDSM_X4(b0, b1r, b2r, b3, w1b + kt * 32);   // shared by both mt
#pragma unroll
            for (int mt = 0; mt < 2; ++mt) {
                const uint32_t* aa =
                    reinterpret_cast<const uint32_t*>(&a_cur[mt][kt]);
                mma_bf16(c1[mt][0], aa, b0, b1r);
                mma_bf16(c1[mt][1], aa, b2r, b3);
            }
        }

        // W2 fragments (last smem reads of stage s), shared by both mt
        uint32_t d[4][4];
#pragma unroll
        for (int p = 0; p < 4; ++p)
            LDSM_X4(d[p][0], d[p][1], d[p][2], d[p][3],
                    w2b + p * 16 * W2_STRIDE);

        MBAR_ARRIVE(mb_empty + 8 * s);     // stage s free for producer

        // relu + cvt -> GEMM2 A-frags; GEMM2: z[32,64] += tmp @ W2
#pragma unroll
        for (int mt = 0; mt < 2; ++mt) {
#pragma unroll
            for (int nt = 0; nt < 2; ++nt)
#pragma unroll
                for (int u = 0; u < 4; ++u)
                    c1[mt][nt][u] = fmaxf(c1[mt][nt][u], 0.f);
            uint32_t a2[4];
            __nv_bfloat162 p0 = __floats2bfloat162_rn(c1[mt][0][0], c1[mt][0][1]);
            __nv_bfloat162 p1 = __floats2bfloat162_rn(c1[mt][0][2], c1[mt][0][3]);
            __nv_bfloat162 p2 = __floats2bfloat162_rn(c1[mt][1][0], c1[mt][1][1]);
            __nv_bfloat162 p3 = __floats2bfloat162_rn(c1[mt][1][2], c1[mt][1][3]);
            a2[0] = *reinterpret_cast<uint32_t*>(&p0);
            a2[1] = *reinterpret_cast<uint32_t*>(&p1);
            a2[2] = *reinterpret_cast<uint32_t*>(&p2);
            a2[3] = *reinterpret_cast<uint32_t*>(&p3);
#pragma unroll
            for (int p = 0; p < 4; ++p) {
                mma_bf16(zacc[mt][2 * p + 0], a2, d[p][0], d[p][1]);
                mma_bf16(zacc[mt][2 * p + 1], a2, d[p][2], d[p][3]);
            }
        }

#pragma unroll
        for (int mt = 0; mt < 2; ++mt)
#pragma unroll
            for (int kt = 0; kt < 4; ++kt) a_cur[mt][kt] = a_nxt[mt][kt];
    }

    __syncthreads();         // join with producer; smem ring dead

    // ---- fused CE head -----------------------------------------------------
    // W3[i] fp32 [e][n] -> smem bf16 [n][e] (rows 144B)
    {
        const float4* w3p =
            reinterpret_cast<const float4*>(w3g + (size_t)i * E_ * N_);
        __nv_bfloat16* W3S =
            reinterpret_cast<__nv_bfloat16*>(smem + OFF_W3S);
#pragma unroll
        for (int it = 0; it < 16; ++it) {
            int idx = it * 256 + tid;      // 4096 float4 total
            float4 f = w3p[idx];
            int e = idx >> 6, n0 = (idx & 63) * 4;
            W3S[(n0 + 0) * 72 + e] = __float2bfloat16(f.x);
            W3S[(n0 + 1) * 72 + e] = __float2bfloat16(f.y);
            W3S[(n0 + 2) * 72 + e] = __float2bfloat16(f.z);
            W3S[(n0 + 3) * 72 + e] = __float2bfloat16(f.w);
        }
    }

    // z + bias2 -> bf16 A-fragments
    uint32_t az[2][4][4];
#pragma unroll
    for (int mt = 0; mt < 2; ++mt)
#pragma unroll
        for (int kt = 0; kt < 4; ++kt) {
            float v[2][4];
#pragma unroll
            for (int p = 0; p < 2; ++p) {
                int nt = 2 * kt + p;
                float bx = sb2[nt * 8 + 2 * q], by = sb2[nt * 8 + 2 * q + 1];
                v[p][0] = zacc[mt][nt][0] + bx; v[p][1] = zacc[mt][nt][1] + by;
                v[p][2] = zacc[mt][nt][2] + bx; v[p][3] = zacc[mt][nt][3] + by;
            }
            __nv_bfloat162 p0 = __floats2bfloat162_rn(v[0][0], v[0][1]);
            __nv_bfloat162 p1 = __floats2bfloat162_rn(v[0][2], v[0][3]);
            __nv_bfloat162 p2 = __floats2bfloat162_rn(v[1][0], v[1][1]);
            __nv_bfloat162 p3 = __floats2bfloat162_rn(v[1][2], v[1][3]);
            az[mt][kt][0] = *reinterpret_cast<uint32_t*>(&p0);
            az[mt][kt][1] = *reinterpret_cast<uint32_t*>(&p1);
            az[mt][kt][2] = *reinterpret_cast<uint32_t*>(&p2);
            az[mt][kt][3] = *reinterpret_cast<uint32_t*>(&p3);
        }

    int xv[2][2];
#pragma unroll
    for (int mt = 0; mt < 2; ++mt) {
        xv[mt][0] = x[(size_t)(w * 32 + mt * 16 + r4) * T_ + i];
        xv[mt][1] = x[(size_t)(w * 32 + mt * 16 + r4 + 8) * T_ + i];
    }

    __syncthreads();         // W3S ready

    const uint32_t w3_off = smem_u32 + OFF_W3S + brow * 144 + bcol;
    float sum[2][2]    = {{0.f, 0.f}, {0.f, 0.f}};
    float picked[2][2] = {{0.f, 0.f}, {0.f, 0.f}};

#pragma unroll
    for (int n0 = 0; n0 < 4; ++n0) {
        float c[2][8][4];
#pragma unroll
        for (int mt = 0; mt < 2; ++mt)
#pragma unroll
            for (int nt = 0; nt < 8; ++nt)
#pragma unroll
                for (int u = 0; u < 4; ++u) c[mt][nt][u] = 0.f;
#pragma unroll
        for (int ntp = 0; ntp < 4; ++ntp) {
#pragma unroll
            for (int kt = 0; kt < 4; ++kt) {
                uint32_t b0, b1r, b2r, b3;
                LDSM_X4(b0, b1r, b2r, b3,
                        w3_off + (n0 * 64 + ntp * 16) * 144 + kt * 32);
#pragma unroll
                for (int mt = 0; mt < 2; ++mt) {
                    mma_bf16(c[mt][2 * ntp + 0], az[mt][kt], b0, b1r);
                    mma_bf16(c[mt][2 * ntp + 1], az[mt][kt], b2r, b3);
                }
            }
        }
#pragma unroll
        for (int mt = 0; mt < 2; ++mt)
#pragma unroll
            for (int nt = 0; nt < 8; ++nt)
#pragma unroll
                for (int u = 0; u < 4; ++u) {
                    int n = n0 * 64 + nt * 8 + 2 * q + (u & 1);
                    int hh = u >> 1;
                    float v = c[mt][nt][u];
                    sum[mt][hh] += __expf(v);
                    if (n == xv[mt][hh]) picked[mt][hh] = v;
                }
    }

#pragma unroll
    for (int mt = 0; mt < 2; ++mt)
#pragma unroll
        for (int hh = 0; hh < 2; ++hh) {
            float sv = sum[mt][hh], pv = picked[mt][hh];
            sv += __shfl_xor_sync(0xffffffffu, sv, 1);
            sv += __shfl_xor_sync(0xffffffffu, sv, 2);
            pv += __shfl_xor_sync(0xffffffffu, pv, 1);
            pv += __shfl_xor_sync(0xffffffffu, pv, 2);
            if (q == 0) {
                int row = w * 32 + mt * 16 + r4 + 8 * hh;
                out[(size_t)row * T_ + i] = __logf(sv) - pv;
            }
        }
}

// ---------------------------------------------------------------------------
extern "C" void kernel_launch(void* const* d_in, const int* in_sizes, int n_in,
                              void* d_out, int out_size) {
    const int*   x    = (const int*)  d_in[0];  // [B,T]
    const float* emb  = (const float*)d_in[1];  // [N*T,E]
    const float* lin1 = (const float*)d_in[2];  // [T,T,E,H]
    const float* b1   = (const float*)d_in[3];  // [T,T,H]
    const float* lin2 = (const float*)d_in[4];  // [T,(T-1)*H,E]
    const float* b2   = (const float*)d_in[5];  // [T,E]
    const float* w3   = (const float*)d_in[6];  // [T,E,N]
    float* out = (float*)d_out;                 // [B,T]

    cudaFuncSetAttribute(fused_all_kernel,
                         cudaFuncAttributeMaxDynamicSharedMemorySize,
                         SMEM_TOTAL);

    gather_frag_kernel<<<T_, 256>>>(x, emb);
    fused_all_kernel<<<T_, NTHREADS, SMEM_TOTAL>>>(lin1, b1, lin2, b2,
                                                   w3, x, out);
}

// round 17
// speedup vs baseline: 1.1027x; 1.1027x over previous
#include <cuda_runtime.h>
#include <cuda_bf16.h>
#include <cstdint>

// Problem constants
constexpr int B_ = 256;   // batch
constexpr int T_ = 128;   // trees
constexpr int N_ = 256;   // nodes (= classes)
constexpr int E_ = 64;    // embedding
constexpr int H_ = 16;    // hidden
constexpr int K2_ = (T_ - 1) * H_;  // 2032

// Fragment-ordered gathered embeddings:
// g_bef[ ((j*16 + strip)*4 + kt)*32 + lane ] = uint4 A-frag regs {a0,a1,a2,a3}
__device__ uint4 g_bef[T_ * 16 * 4 * 32];   // 4 MB

// ---------------------------------------------------------------------------
// mma.sync m16n8k16 bf16 (fp32 accum) + ldmatrix + mbarrier helpers
// ---------------------------------------------------------------------------
__device__ __forceinline__ void mma_bf16(float* c, const uint32_t* a,
                                         uint32_t b0, uint32_t b1) {
    asm volatile(
        "mma.sync.aligned.m16n8k16.row.col.f32.bf16.bf16.f32 "
        "{%0,%1,%2,%3}, {%4,%5,%6,%7}, {%8,%9}, {%0,%1,%2,%3};"
        : "+f"(c[0]), "+f"(c[1]), "+f"(c[2]), "+f"(c[3])
        : "r"(a[0]), "r"(a[1]), "r"(a[2]), "r"(a[3]), "r"(b0), "r"(b1));
}

#define LDSM_X4(r0, r1, r2, r3, addr)                                     \
    asm volatile("ldmatrix.sync.aligned.m8n8.x4.shared.b16 "              \
                 "{%0,%1,%2,%3}, [%4];"                                   \
                 : "=r"(r0), "=r"(r1), "=r"(r2), "=r"(r3) : "r"(addr))

#define MBAR_INIT(a, c) \
    asm volatile("mbarrier.init.shared.b64 [%0], %1;" :: "r"(a), "r"(c) : "memory")
#define MBAR_ARRIVE(a) \
    asm volatile("mbarrier.arrive.shared.b64 _, [%0];" :: "r"(a) : "memory")
#define MBAR_WAIT(a, par) do {                                              \
    uint32_t _m = (a), _p = (par), _d;                                      \
    asm volatile("{\n\t.reg .pred p;\n\t"                                   \
        "mbarrier.try_wait.parity.acquire.cta.shared::cta.b64 p, [%1], %2;\n\t" \
        "selp.b32 %0, 1, 0, p;\n\t}" : "=r"(_d) : "r"(_m), "r"(_p) : "memory"); \
    if (!_d) {                                                              \
        asm volatile("{\n\t.reg .pred P1;\n\tWL_%=:\n\t"                    \
            "mbarrier.try_wait.parity.acquire.cta.shared::cta.b64 P1, [%0], %1, 0x989680;\n\t" \
            "@P1 bra.uni WD_%=;\n\tbra.uni WL_%=;\n\tWD_%=:\n\t}"           \
            :: "r"(_m), "r"(_p) : "memory");                                \
    }                                                                       \
} while (0)

// ---------------------------------------------------------------------------
// Kernel 1: gather embeddings (shifted index) AND emit A-fragments.
// ---------------------------------------------------------------------------
__global__ void __launch_bounds__(256)
gather_frag_kernel(const int* __restrict__ x,
                   const float* __restrict__ emb) {
    __shared__ __align__(16) char sm[256 * 144];
    const int j    = blockIdx.x;
    const int tid  = threadIdx.x;
    const int w    = tid >> 5;
    const int lane = tid & 31;
    const uint32_t smem_u32 = (uint32_t)__cvta_generic_to_shared(sm);

    {
        const int row = x[tid * T_ + j] + j * N_;
        const float4* src =
            reinterpret_cast<const float4*>(emb + (size_t)row * E_);
        char* dst = sm + tid * 144;
#pragma unroll
        for (int k = 0; k < 8; ++k) {
            float4 f0 = src[2 * k], f1 = src[2 * k + 1];
            __nv_bfloat162 p0 = __floats2bfloat162_rn(f0.x, f0.y);
            __nv_bfloat162 p1 = __floats2bfloat162_rn(f0.z, f0.w);
            __nv_bfloat162 p2 = __floats2bfloat162_rn(f1.x, f1.y);
            __nv_bfloat162 p3 = __floats2bfloat162_rn(f1.z, f1.w);
            uint4 v;
            v.x = *reinterpret_cast<uint32_t*>(&p0);
            v.y = *reinterpret_cast<uint32_t*>(&p1);
            v.z = *reinterpret_cast<uint32_t*>(&p2);
            v.w = *reinterpret_cast<uint32_t*>(&p3);
            *reinterpret_cast<uint4*>(dst + k * 16) = v;
        }
    }
    __syncthreads();

#pragma unroll
    for (int sg = 0; sg < 2; ++sg) {
        const int s = w + 8 * sg;
        const uint32_t a_off = smem_u32 +
            (s * 16 + (lane & 15)) * 144 + (lane >> 4) * 16;
#pragma unroll
        for (int kt = 0; kt < 4; ++kt) {
            uint32_t r0, r1, r2, r3;
            LDSM_X4(r0, r1, r2, r3, a_off + kt * 32);
            uint4 v; v.x = r0; v.y = r1; v.z = r2; v.w = r3;
            g_bef[((size_t)(j * 16 + s) * 4 + kt) * 32 + lane] = v;
        }
    }
}

// ---------------------------------------------------------------------------
// Fused-kernel SMEM layout (bytes)
// ---------------------------------------------------------------------------
constexpr int W1_STRIDE = 144;              // [h][e] bf16
constexpr int W1_BUF    = 16 * W1_STRIDE;   // 2304
constexpr int W2_STRIDE = 48;               // [e][h] bf16
constexpr int W2_BUF    = 64 * W2_STRIDE;   // 3072
constexpr int NSTAGE    = 4;                // stages; each holds 2 j's
constexpr int OFF_MBAR  = 0;                          // 8 mbarriers (64B)
constexpr int OFF_W1    = 64;                         // 8 slots
constexpr int OFF_W2    = OFF_W1 + 2 * NSTAGE * W1_BUF;   // 18496
constexpr int OFF_B1    = OFF_W2 + 2 * NSTAGE * W2_BUF;   // 43072
constexpr int OFF_B2    = OFF_B1 + T_ * H_ * 4;           // 51264
constexpr int OFF_W3S   = 51520;                          // 256 rows x 144B
constexpr int SMEM_TOTAL = OFF_W3S + 256 * 144;           // 88384

constexpr int NTHREADS  = 576;   // 16 consumer warps + 2 producer warps

// ---------------------------------------------------------------------------
// Kernel 2: warp-specialized fused stages 2..7. CTA = tree i.
// Consumers (warps 0-15): m16 strip each, A via direct LDG of g_bef,
//   W via LDSM from a 4-stage x 2-j mbarrier ring (wait/arrive per PAIR).
// Producers (warps 16-17): LDG fp32 weights -> cvt bf16 -> STS ring.
// NO __syncthreads in mainloop. GEMM1 split into 2 independent mma chains.
// ---------------------------------------------------------------------------
__global__ void __launch_bounds__(NTHREADS, 1)
fused_all_kernel(const float* __restrict__ lin1,   // [T,T,E,H]
                 const float* __restrict__ b1,     // [T,T,H]
                 const float* __restrict__ lin2,   // [T,(T-1)*H,E]
                 const float* __restrict__ b2,     // [T,E]
                 const float* __restrict__ w3g,    // [T,E,N]
                 const int*   __restrict__ x,      // [B,T]
                 float* __restrict__ out) {        // [B,T]
    extern __shared__ char smem[];
    const int i    = blockIdx.x;
    const int tid  = threadIdx.x;
    const int w    = tid >> 5;
    const int lane = tid & 31;
    const int q    = lane & 3;
    const int r4   = lane >> 2;

    float* sb1 = reinterpret_cast<float*>(smem + OFF_B1);
    float* sb2 = reinterpret_cast<float*>(smem + OFF_B2);
    const uint32_t smem_u32 = (uint32_t)__cvta_generic_to_shared(smem);
    const uint32_t mb_full  = smem_u32 + OFF_MBAR;        // full[s]  = +8s
    const uint32_t mb_empty = smem_u32 + OFF_MBAR + 32;   // empty[s] = +8s

    auto jof = [&](int jj) { return jj + (jj >= i); };

    // ---- init: mbarriers + biases, one barrier before pipeline start -------
    if (tid == 0) {
#pragma unroll
        for (int s = 0; s < NSTAGE; ++s) {
            MBAR_INIT(mb_full + 8 * s, 64);    // 64 producer threads arrive
            MBAR_INIT(mb_empty + 8 * s, 512);  // 512 consumer threads arrive
        }
    }
    if (tid < 512) {
#pragma unroll
        for (int u = 0; u < 4; ++u)
            sb1[tid + 512 * u] = b1[(size_t)i * T_ * H_ + tid + 512 * u];
        if (tid < E_) sb2[tid] = b2[(size_t)i * E_ + tid];
    }
    __syncthreads();

    if (w >= 16) {
        // =================== PRODUCER (warps 16,17) =========================
        const int ptid = tid - 512;            // 0..63
        for (int pp = 0; pp < 64; ++pp) {      // pair index: jj = 2pp, 2pp+1
            const int s = pp & 3;
            MBAR_WAIT(mb_empty + 8 * s, ((pp >> 2) & 1) ^ 1);

#pragma unroll
            for (int u2 = 0; u2 < 2; ++u2) {
                const int jj = 2 * pp + u2;
                if (jj >= T_ - 1) break;
                const int j = jof(jj);
                const int slot = s * 2 + u2;

                // W1[i,j]: thread ptid owns e=ptid (16 floats h=0..15)
                {
                    const float4* p = reinterpret_cast<const float4*>(
                        lin1 + (size_t)(i * T_ + j) * (E_ * H_) + ptid * 16);
                    __nv_bfloat16* w1 = reinterpret_cast<__nv_bfloat16*>(
                        smem + OFF_W1 + slot * W1_BUF);
#pragma unroll
                    for (int v4 = 0; v4 < 4; ++v4) {
                        float4 f = p[v4];
                        const float* fv = reinterpret_cast<const float*>(&f);
#pragma unroll
                        for (int u = 0; u < 4; ++u) {
                            int h = v4 * 4 + u;
                            w1[h * (W1_STRIDE / 2) + ptid] =
                                __float2bfloat16(fv[u]);
                        }
                    }
                }
                // W2 rows: thread ptid owns idx = ptid*16 + 0..15
                {
                    const int kk = (j < i) ? j : j - 1;
                    const float4* p = reinterpret_cast<const float4*>(
                        lin2 + ((size_t)i * K2_ + (size_t)kk * H_) * E_ +
                        ptid * 16);
                    __nv_bfloat16* w2 = reinterpret_cast<__nv_bfloat16*>(
                        smem + OFF_W2 + slot * W2_BUF);
#pragma unroll
                    for (int v4 = 0; v4 < 4; ++v4) {
                        float4 f = p[v4];
                        const float* fv = reinterpret_cast<const float*>(&f);
#pragma unroll
                        for (int u = 0; u < 4; ++u) {
                            int idx = ptid * 16 + v4 * 4 + u;
                            int k = idx >> 6, e = idx & 63;
                            w2[e * (W2_STRIDE / 2) + k] =
                                __float2bfloat16(fv[u]);
                        }
                    }
                }
            }
            MBAR_ARRIVE(mb_full + 8 * s);      // release: STS visible
        }
    } else {
        // =================== CONSUMER (warps 0-15) ==========================
        const int brow = (lane & 7) + ((lane >> 1) & 8);
        const int bcol = ((lane >> 3) & 1) * 16;
        const uint32_t w1_off = smem_u32 + OFF_W1 + brow * W1_STRIDE + bcol;
        const uint32_t w2_off = smem_u32 + OFF_W2 + brow * W2_STRIDE + bcol;

        auto ldg_a = [&](int j, uint4* a) {
            const uint4* p = g_bef + (size_t)(j * 16 + w) * 4 * 32 + lane;
#pragma unroll
            for (int kt = 0; kt < 4; ++kt) a[kt] = p[kt * 32];
        };

        uint4 a_cur[4], a_nxt[4];
        ldg_a(jof(0), a_cur);

        float zacc[8][4];
#pragma unroll
        for (int nt = 0; nt < 8; ++nt)
#pragma unroll
            for (int s = 0; s < 4; ++s) zacc[nt][s] = 0.f;

        for (int jj = 0; jj < T_ - 1; ++jj) {
            const int pp = jj >> 1;
            const int s  = pp & 3;
            const int j  = jof(jj);

            if (jj + 1 < T_ - 1) ldg_a(jof(jj + 1), a_nxt);

            if ((jj & 1) == 0)
                MBAR_WAIT(mb_full + 8 * s, (pp >> 2) & 1);   // acquire pair

            const int slot = s * 2 + (jj & 1);
            const uint32_t w1b = w1_off + slot * W1_BUF;
            const uint32_t w2b = w2_off + slot * W2_BUF;

            // GEMM1 split into two 2-deep chains: c1a (kt 0,1), c1b (kt 2,3)
            float c1a[2][4], c1b[2][4];
#pragma unroll
            for (int nt = 0; nt < 2; ++nt) {
                float bv0 = sb1[j * H_ + nt * 8 + 2 * q];
                float bv1 = sb1[j * H_ + nt * 8 + 2 * q + 1];
                c1a[nt][0] = bv0; c1a[nt][1] = bv1;
                c1a[nt][2] = bv0; c1a[nt][3] = bv1;
#pragma unroll
                for (int u = 0; u < 4; ++u) c1b[nt][u] = 0.f;
            }
#pragma unroll
            for (int kt = 0; kt < 2; ++kt) {
                uint32_t b0, b1r, b2r, b3;
                LDSM_X4(b0, b1r, b2r, b3, w1b + kt * 32);
                const uint32_t* aa =
                    reinterpret_cast<const uint32_t*>(&a_cur[kt]);
                mma_bf16(c1a[0], aa, b0, b1r);
                mma_bf16(c1a[1], aa, b2r, b3);
            }
#pragma unroll
            for (int kt = 2; kt < 4; ++kt) {
                uint32_t b0, b1r, b2r, b3;
                LDSM_X4(b0, b1r, b2r, b3, w1b + kt * 32);
                const uint32_t* aa =
                    reinterpret_cast<const uint32_t*>(&a_cur[kt]);
                mma_bf16(c1b[0], aa, b0, b1r);
                mma_bf16(c1b[1], aa, b2r, b3);
            }

            // W2 fragments (last smem reads of this slot)
            uint32_t d[4][4];
#pragma unroll
            for (int p = 0; p < 4; ++p)
                LDSM_X4(d[p][0], d[p][1], d[p][2], d[p][3],
                        w2b + p * 16 * W2_STRIDE);

            // arrive once per PAIR, after the stage's last j is consumed
            if ((jj & 1) == 1 || jj == T_ - 2)
                MBAR_ARRIVE(mb_empty + 8 * s);

            // merge chains + relu + cvt -> GEMM2 A-frag
            uint32_t a2[4];
            {
                float m[2][4];
#pragma unroll
                for (int nt = 0; nt < 2; ++nt)
#pragma unroll
                    for (int u = 0; u < 4; ++u)
                        m[nt][u] = fmaxf(c1a[nt][u] + c1b[nt][u], 0.f);
                __nv_bfloat162 p0 = __floats2bfloat162_rn(m[0][0], m[0][1]);
                __nv_bfloat162 p1 = __floats2bfloat162_rn(m[0][2], m[0][3]);
                __nv_bfloat162 p2 = __floats2bfloat162_rn(m[1][0], m[1][1]);
                __nv_bfloat162 p3 = __floats2bfloat162_rn(m[1][2], m[1][3]);
                a2[0] = *reinterpret_cast<uint32_t*>(&p0);
                a2[1] = *reinterpret_cast<uint32_t*>(&p1);
                a2[2] = *reinterpret_cast<uint32_t*>(&p2);
                a2[3] = *reinterpret_cast<uint32_t*>(&p3);
            }

            // GEMM2: z[16,64] += tmp[16,16] @ W2[16,64]
#pragma unroll
            for (int p = 0; p < 4; ++p) {
                mma_bf16(zacc[2 * p + 0], a2, d[p][0], d[p][1]);
                mma_bf16(zacc[2 * p + 1], a2, d[p][2], d[p][3]);
            }

#pragma unroll
            for (int kt = 0; kt < 4; ++kt) a_cur[kt] = a_nxt[kt];
        }

        __syncthreads();         // join with producers; smem ring dead

        // ---- fused CE head -------------------------------------------------
        // W3[i] fp32 [e][n] -> smem bf16 [n][e] (rows 144B)
        {
            const float4* w3p =
                reinterpret_cast<const float4*>(w3g + (size_t)i * E_ * N_);
            __nv_bfloat16* W3S =
                reinterpret_cast<__nv_bfloat16*>(smem + OFF_W3S);
#pragma unroll
            for (int it = 0; it < 8; ++it) {
                int idx = it * 512 + tid;      // 4096 float4 total
                float4 f = w3p[idx];
                int e = idx >> 6, n0 = (idx & 63) * 4;
                W3S[(n0 + 0) * 72 + e] = __float2bfloat16(f.x);
                W3S[(n0 + 1) * 72 + e] = __float2bfloat16(f.y);
                W3S[(n0 + 2) * 72 + e] = __float2bfloat16(f.z);
                W3S[(n0 + 3) * 72 + e] = __float2bfloat16(f.w);
            }
        }

        uint32_t az[4][4];
#pragma unroll
        for (int kt = 0; kt < 4; ++kt) {
            float v[2][4];
#pragma unroll
            for (int p = 0; p < 2; ++p) {
                int nt = 2 * kt + p;
                float bx = sb2[nt * 8 + 2 * q], by = sb2[nt * 8 + 2 * q + 1];
                v[p][0] = zacc[nt][0] + bx; v[p][1] = zacc[nt][1] + by;
                v[p][2] = zacc[nt][2] + bx; v[p][3] = zacc[nt][3] + by;
            }
            __nv_bfloat162 p0 = __floats2bfloat162_rn(v[0][0], v[0][1]);
            __nv_bfloat162 p1 = __floats2bfloat162_rn(v[0][2], v[0][3]);
            __nv_bfloat162 p2 = __floats2bfloat162_rn(v[1][0], v[1][1]);
            __nv_bfloat162 p3 = __floats2bfloat162_rn(v[1][2], v[1][3]);
            az[kt][0] = *reinterpret_cast<uint32_t*>(&p0);
            az[kt][1] = *reinterpret_cast<uint32_t*>(&p1);
            az[kt][2] = *reinterpret_cast<uint32_t*>(&p2);
            az[kt][3] = *reinterpret_cast<uint32_t*>(&p3);
        }

        int xv[2];
        xv[0] = x[(size_t)(w * 16 + r4) * T_ + i];
        xv[1] = x[(size_t)(w * 16 + r4 + 8) * T_ + i];

        __syncthreads();         // W3S ready

        const uint32_t w3_off = smem_u32 + OFF_W3S + brow * 144 + bcol;
        float sum[2] = {0.f, 0.f};
        float picked[2] = {0.f, 0.f};

#pragma unroll
        for (int n0 = 0; n0 < 4; ++n0) {
            float c[8][4];
#pragma unroll
            for (int nt = 0; nt < 8; ++nt)
#pragma unroll
                for (int u = 0; u < 4; ++u) c[nt][u] = 0.f;
#pragma unroll
            for (int ntp = 0; ntp < 4; ++ntp) {
#pragma unroll
                for (int kt = 0; kt < 4; ++kt) {
                    uint32_t b0, b1r, b2r, b3;
                    LDSM_X4(b0, b1r, b2r, b3,
                            w3_off + (n0 * 64 + ntp * 16) * 144 + kt * 32);
                    mma_bf16(c[2 * ntp + 0], az[kt], b0, b1r);
                    mma_bf16(c[2 * ntp + 1], az[kt], b2r, b3);
                }
            }
#pragma unroll
            for (int nt = 0; nt < 8; ++nt)
#pragma unroll
                for (int u = 0; u < 4; ++u) {
                    int n = n0 * 64 + nt * 8 + 2 * q + (u & 1);
                    int hh = u >> 1;
                    float v = c[nt][u];
                    sum[hh] += __expf(v);
                    if (n == xv[hh]) picked[hh] = v;
                }
        }

#pragma unroll
        for (int hh = 0; hh < 2; ++hh) {
            float sv = sum[hh], pv = picked[hh];
            sv += __shfl_xor_sync(0xffffffffu, sv, 1);
            sv += __shfl_xor_sync(0xffffffffu, sv, 2);
            pv += __shfl_xor_sync(0xffffffffu, pv, 1);
            pv += __shfl_xor_sync(0xffffffffu, pv, 2);
            if (q == 0) {
                int row = w * 16 + r4 + 8 * hh;
                out[(size_t)row * T_ + i] = __logf(sv) - pv;
            }
        }
        return;
    }

    // producers: join the two consumer barriers, then exit
    __syncthreads();
    __syncthreads();
}

// ---------------------------------------------------------------------------
extern "C" void kernel_launch(void* const* d_in, const int* in_sizes, int n_in,
                              void* d_out, int out_size) {
    const int*   x    = (const int*)  d_in[0];  // [B,T]
    const float* emb  = (const float*)d_in[1];  // [N*T,E]
    const float* lin1 = (const float*)d_in[2];  // [T,T,E,H]
    const float* b1   = (const float*)d_in[3];  // [T,T,H]
    const float* lin2 = (const float*)d_in[4];  // [T,(T-1)*H,E]
    const float* b2   = (const float*)d_in[5];  // [T,E]
    const float* w3   = (const float*)d_in[6];  // [T,E,N]
    float* out = (float*)d_out;                 // [B,T]

    cudaFuncSetAttribute(fused_all_kernel,
                         cudaFuncAttributeMaxDynamicSharedMemorySize,
                         SMEM_TOTAL);

    gather_frag_kernel<<<T_, 256>>>(x, emb);
    fused_all_kernel<<<T_, NTHREADS, SMEM_TOTAL>>>(lin1, b1, lin2, b2,
                                                   w3, x, out);
}